// round 2
// baseline (speedup 1.0000x reference)
#include <cuda_runtime.h>
#include <cstdint>

// Problem constants (fixed-shape problem)
#define NN 100000
#define FF 32
#define DD 3
#define OO 32

// Scratch: node-feature accumulator + transposed params
__device__ float g_accum[NN * FF];
__device__ float g_mu_t[DD * FF];   // [d][f]
__device__ float g_c_t[DD * FF];    // [d][f] = -0.5 / (1e-14 + sigma^2)
__device__ int   g_is64;            // edge_index dtype flag (1 = int64)

// ---------------------------------------------------------------------------
// Prep: transpose mu, precompute gaussian coefficients, probe edge dtype
// ---------------------------------------------------------------------------
__global__ void prep_kernel(const float* __restrict__ mu,
                            const float* __restrict__ sigma,
                            const int* __restrict__ ei32,
                            int total_elems) {
    int t = threadIdx.x;
    if (t < DD * FF) {
        int d = t / FF;
        int f = t % FF;
        float m = mu[f * DD + d];
        float s = sigma[f * DD + d];
        g_mu_t[d * FF + f] = m;
        g_c_t[d * FF + f]  = -0.5f / (1e-14f + s * s);
    }
    if (t == 0) {
        // If int64 little-endian with values < 2^31, every odd 32-bit word
        // of the raw buffer is zero. Probe 128 odd words.
        int all_zero = 1;
        int limit = 2 * total_elems;  // raw int32 words if int64
        for (int i = 1; i < 257 && i < limit; i += 2) {
            if (ei32[i] != 0) { all_zero = 0; break; }
        }
        g_is64 = all_zero;
    }
}

// ---------------------------------------------------------------------------
// Zero the accumulator (vectorized)
// ---------------------------------------------------------------------------
__global__ void zero_kernel() {
    int i = blockIdx.x * blockDim.x + threadIdx.x;
    int total4 = (NN * FF) / 4;
    float4 z = make_float4(0.f, 0.f, 0.f, 0.f);
    float4* p = reinterpret_cast<float4*>(g_accum);
    for (; i < total4; i += gridDim.x * blockDim.x) p[i] = z;
}

// ---------------------------------------------------------------------------
// Edge kernel: one warp per edge (grid-stride over edges).
// lane = feature channel f. Compute gaussian weight, gather x[col], scatter
// into g_accum[row] with atomicAdd (compiles to REDG, no return).
// ---------------------------------------------------------------------------
__global__ void __launch_bounds__(256) edge_kernel(
    const float* __restrict__ x,
    const void* __restrict__ edge_index,
    const float* __restrict__ pseudo,
    int E) {
    const int lane = threadIdx.x & 31;
    const int warp = (blockIdx.x * blockDim.x + threadIdx.x) >> 5;
    const int nwarps = (gridDim.x * blockDim.x) >> 5;

    const int is64 = g_is64;
    const int* __restrict__ ei32 = (const int*)edge_index;
    const long long* __restrict__ ei64 = (const long long*)edge_index;

    // Per-lane gaussian params, held in registers across the edge loop
    const float mu0 = g_mu_t[0 * FF + lane];
    const float mu1 = g_mu_t[1 * FF + lane];
    const float mu2 = g_mu_t[2 * FF + lane];
    const float c0  = g_c_t[0 * FF + lane];
    const float c1  = g_c_t[1 * FF + lane];
    const float c2  = g_c_t[2 * FF + lane];

    for (int e = warp; e < E; e += nwarps) {
        int r, c;
        if (is64) {
            r = (int)ei64[e];
            c = (int)ei64[(size_t)E + e];
        } else {
            r = ei32[e];
            c = ei32[(size_t)E + e];
        }
        float p0 = pseudo[(size_t)e * 3 + 0];
        float p1 = pseudo[(size_t)e * 3 + 1];
        float p2 = pseudo[(size_t)e * 3 + 2];

        float d0 = p0 - mu0;
        float d1 = p1 - mu1;
        float d2 = p2 - mu2;
        float logw = d0 * d0 * c0 + d1 * d1 * c1 + d2 * d2 * c2;
        float g = __expf(logw);

        float v = x[(size_t)c * FF + lane] * g;          // coalesced 128B gather
        atomicAdd(&g_accum[(size_t)r * FF + lane], v);   // REDG scatter
    }
}

// ---------------------------------------------------------------------------
// Linear epilogue: one warp per node, lane = output channel o.
// out[n,o] = b[o] + sum_f accum[n,f] * W[o,f]
// ---------------------------------------------------------------------------
__global__ void __launch_bounds__(256) linear_kernel(
    const float* __restrict__ W,
    const float* __restrict__ b,
    float* __restrict__ out,
    int N) {
    const int lane = threadIdx.x & 31;
    const int warp = (blockIdx.x * blockDim.x + threadIdx.x) >> 5;
    if (warp >= N) return;

    // Each lane holds row o=lane of W in registers (4KB total, L1/L2 hot)
    float w[FF];
#pragma unroll
    for (int f = 0; f < FF; f++) w[f] = W[lane * FF + f];
    float bias = b[lane];

    float a = g_accum[(size_t)warp * FF + lane];   // coalesced row load
    float s = bias;
#pragma unroll
    for (int f = 0; f < FF; f++)
        s += __shfl_sync(0xffffffffu, a, f) * w[f];

    out[(size_t)warp * OO + lane] = s;
}

// ---------------------------------------------------------------------------
extern "C" void kernel_launch(void* const* d_in, const int* in_sizes, int n_in,
                              void* d_out, int out_size) {
    const float* x   = (const float*)d_in[0];
    const void*  ei  = d_in[1];
    const float* ps  = (const float*)d_in[2];
    const float* mu  = (const float*)d_in[3];
    const float* sg  = (const float*)d_in[4];
    const float* W   = (const float*)d_in[5];
    const float* b   = (const float*)d_in[6];
    float*       out = (float*)d_out;

    const int E = in_sizes[1] / 2;
    const int N = in_sizes[0] / FF;

    prep_kernel<<<1, 128>>>(mu, sg, (const int*)ei, in_sizes[1]);
    zero_kernel<<<800, 256>>>();

    edge_kernel<<<148 * 8, 256>>>(x, ei, ps, E);

    int blocks = (N * 32 + 255) / 256;
    linear_kernel<<<blocks, 256>>>(W, b, out, N);
}

// round 3
// speedup vs baseline: 3.8348x; 3.8348x over previous
#include <cuda_runtime.h>
#include <cstdint>

#define NN 100000
#define FF 32
#define DD 3
#define OO 32

__device__ float g_accum[NN * FF];
__device__ float g_mu_t[DD * FF];   // [d][f]
__device__ float g_c_t[DD * FF];    // [d][f] = -0.5 / (1e-14 + sigma^2)
__device__ int   g_is64;            // edge_index dtype flag (1 = int64)

// ---------------------------------------------------------------------------
// Prep: transpose mu, precompute gaussian coefficients, probe edge dtype
// ---------------------------------------------------------------------------
__global__ void prep_kernel(const float* __restrict__ mu,
                            const float* __restrict__ sigma,
                            const int* __restrict__ ei32,
                            int total_elems) {
    int t = threadIdx.x;
    if (t < DD * FF) {
        int d = t / FF;
        int f = t % FF;
        float m = mu[f * DD + d];
        float s = sigma[f * DD + d];
        g_mu_t[d * FF + f] = m;
        g_c_t[d * FF + f]  = -0.5f / (1e-14f + s * s);
    }
    if (t == 0) {
        // int64 little-endian with values < 2^31 => every odd 32-bit word is 0
        int all_zero = 1;
        int limit = 2 * total_elems;
        for (int i = 1; i < 257 && i < limit; i += 2) {
            if (ei32[i] != 0) { all_zero = 0; break; }
        }
        g_is64 = all_zero;
    }
}

// ---------------------------------------------------------------------------
__global__ void zero_kernel() {
    int i = blockIdx.x * blockDim.x + threadIdx.x;
    int total4 = (NN * FF) / 4;
    float4 z = make_float4(0.f, 0.f, 0.f, 0.f);
    float4* p = reinterpret_cast<float4*>(g_accum);
    for (; i < total4; i += gridDim.x * blockDim.x) p[i] = z;
}

// ---------------------------------------------------------------------------
// Edge kernel: one warp per edge, lane = feature channel.
// ---------------------------------------------------------------------------
__global__ void __launch_bounds__(256) edge_kernel(
    const float* __restrict__ x,
    const void* __restrict__ edge_index,
    const float* __restrict__ pseudo,
    int E) {
    const int lane = threadIdx.x & 31;
    const int warp = (blockIdx.x * blockDim.x + threadIdx.x) >> 5;
    const int nwarps = (gridDim.x * blockDim.x) >> 5;

    const int is64 = g_is64;
    const int* __restrict__ ei32 = (const int*)edge_index;
    const long long* __restrict__ ei64 = (const long long*)edge_index;

    const float mu0 = g_mu_t[0 * FF + lane];
    const float mu1 = g_mu_t[1 * FF + lane];
    const float mu2 = g_mu_t[2 * FF + lane];
    const float c0  = g_c_t[0 * FF + lane];
    const float c1  = g_c_t[1 * FF + lane];
    const float c2  = g_c_t[2 * FF + lane];

    for (int e = warp; e < E; e += nwarps) {
        int r, c;
        if (is64) {
            r = (int)ei64[e];
            c = (int)ei64[(size_t)E + e];
        } else {
            r = ei32[e];
            c = ei32[(size_t)E + e];
        }
        float p0 = pseudo[(size_t)e * 3 + 0];
        float p1 = pseudo[(size_t)e * 3 + 1];
        float p2 = pseudo[(size_t)e * 3 + 2];

        float d0 = p0 - mu0;
        float d1 = p1 - mu1;
        float d2 = p2 - mu2;
        float logw = d0 * d0 * c0 + d1 * d1 * c1 + d2 * d2 * c2;
        float g = __expf(logw);

        float v = x[(size_t)c * FF + lane] * g;
        atomicAdd(&g_accum[(size_t)r * FF + lane], v);
    }
}

// ---------------------------------------------------------------------------
// Linear epilogue v2: W staged through padded smem once per block, then
// register-resident per lane. Persistent grid-stride over nodes.
// out[n,o] = b[o] + sum_f accum[n,f] * W[o,f]
// ---------------------------------------------------------------------------
__global__ void __launch_bounds__(256) linear_kernel(
    const float* __restrict__ W,
    const float* __restrict__ b,
    float* __restrict__ out,
    int N) {
    __shared__ float Ws[FF][FF + 1];  // pad: conflict-free row reads
    __shared__ float bs[OO];

    const int tid = threadIdx.x;
    for (int i = tid; i < FF * OO; i += blockDim.x)
        Ws[i >> 5][i & 31] = W[i];    // Ws[o][f], coalesced global load
    if (tid < OO) bs[tid] = b[tid];
    __syncthreads();

    const int lane = tid & 31;
    float w[FF];
#pragma unroll
    for (int f = 0; f < FF; f++) w[f] = Ws[lane][f];  // conflict-free (pad 33)
    const float bias = bs[lane];

    const int warp = (blockIdx.x * blockDim.x + tid) >> 5;
    const int nwarps = (gridDim.x * blockDim.x) >> 5;

    for (int n = warp; n < N; n += nwarps) {
        float a = g_accum[(size_t)n * FF + lane];   // coalesced row load
        float s = bias;
#pragma unroll
        for (int f = 0; f < FF; f++)
            s += __shfl_sync(0xffffffffu, a, f) * w[f];
        out[(size_t)n * OO + lane] = s;             // coalesced store
    }
}

// ---------------------------------------------------------------------------
extern "C" void kernel_launch(void* const* d_in, const int* in_sizes, int n_in,
                              void* d_out, int out_size) {
    const float* x   = (const float*)d_in[0];
    const void*  ei  = d_in[1];
    const float* ps  = (const float*)d_in[2];
    const float* mu  = (const float*)d_in[3];
    const float* sg  = (const float*)d_in[4];
    const float* W   = (const float*)d_in[5];
    const float* b   = (const float*)d_in[6];
    float*       out = (float*)d_out;

    const int E = in_sizes[1] / 2;
    const int N = in_sizes[0] / FF;

    prep_kernel<<<1, 128>>>(mu, sg, (const int*)ei, in_sizes[1]);
    zero_kernel<<<800, 256>>>();

    edge_kernel<<<148 * 8, 256>>>(x, ei, ps, E);

    // persistent grid for linear: 8 blocks/SM x 8 warps each
    linear_kernel<<<148 * 8, 256>>>(W, b, out, N);
}

// round 4
// speedup vs baseline: 5.2429x; 1.3672x over previous
#include <cuda_runtime.h>
#include <cstdint>

#define NN 100000
#define FF 32
#define DD 3
#define OO 32

__device__ float g_accum[NN * FF];
__device__ float g_mu_t[DD * FF];   // [d][f]
__device__ float g_c_t[DD * FF];    // [d][f] = -0.5 / (1e-14 + sigma^2)
__device__ int   g_is64;            // edge_index dtype flag (1 = int64)

// ---------------------------------------------------------------------------
// Prep: transpose mu, precompute gaussian coefficients, probe edge dtype
// ---------------------------------------------------------------------------
__global__ void prep_kernel(const float* __restrict__ mu,
                            const float* __restrict__ sigma,
                            const int* __restrict__ ei32,
                            int total_elems) {
    int t = threadIdx.x;
    if (t < DD * FF) {
        int d = t / FF;
        int f = t % FF;
        float m = mu[f * DD + d];
        float s = sigma[f * DD + d];
        g_mu_t[d * FF + f] = m;
        g_c_t[d * FF + f]  = -0.5f / (1e-14f + s * s);
    }
    if (t == 0) {
        // int64 little-endian with values < 2^31 => every odd 32-bit word is 0
        int all_zero = 1;
        int limit = 2 * total_elems;
        for (int i = 1; i < 257 && i < limit; i += 2) {
            if (ei32[i] != 0) { all_zero = 0; break; }
        }
        g_is64 = all_zero;
    }
}

// ---------------------------------------------------------------------------
__global__ void zero_kernel() {
    int i = blockIdx.x * blockDim.x + threadIdx.x;
    int total4 = (NN * FF) / 4;
    float4 z = make_float4(0.f, 0.f, 0.f, 0.f);
    float4* p = reinterpret_cast<float4*>(g_accum);
    for (; i < total4; i += gridDim.x * blockDim.x) p[i] = z;
}

// ---------------------------------------------------------------------------
// Edge kernel v2: 4 edges per warp-iteration.
//   lane = 8*g + sub :  g   = edge group (0..3)
//                       sub = feature quad (0..7), features fbase=4*sub..+3
// Per lane: compute 4 gaussian-weighted values, one LDG.128 gather,
// one red.global.add.v4.f32 scatter (4x fewer atomic ops than scalar).
// ---------------------------------------------------------------------------
__global__ void __launch_bounds__(256) edge_kernel(
    const float* __restrict__ x,
    const void* __restrict__ edge_index,
    const float* __restrict__ pseudo,
    int E) {
    const int lane  = threadIdx.x & 31;
    const int g     = lane >> 3;      // edge within group of 4
    const int fbase = (lane & 7) * 4; // feature quad
    const int warp  = (blockIdx.x * blockDim.x + threadIdx.x) >> 5;
    const int nwarps = (gridDim.x * blockDim.x) >> 5;

    const int is64 = g_is64;
    const int* __restrict__ ei32 = (const int*)edge_index;
    const long long* __restrict__ ei64 = (const long long*)edge_index;

    // per-lane gaussian params for its 4 features (24 registers)
    float mu0[4], mu1[4], mu2[4], c0[4], c1[4], c2[4];
#pragma unroll
    for (int j = 0; j < 4; j++) {
        mu0[j] = g_mu_t[0 * FF + fbase + j];
        mu1[j] = g_mu_t[1 * FF + fbase + j];
        mu2[j] = g_mu_t[2 * FF + fbase + j];
        c0[j]  = g_c_t[0 * FF + fbase + j];
        c1[j]  = g_c_t[1 * FF + fbase + j];
        c2[j]  = g_c_t[2 * FF + fbase + j];
    }

    for (long long eb = (long long)warp * 4; eb < E; eb += (long long)nwarps * 4) {
        long long e = eb + g;
        if (e >= E) continue;

        int r, c;
        if (is64) {
            r = (int)ei64[e];
            c = (int)ei64[(long long)E + e];
        } else {
            r = ei32[e];
            c = ei32[(long long)E + e];
        }
        float p0 = pseudo[e * 3 + 0];
        float p1 = pseudo[e * 3 + 1];
        float p2 = pseudo[e * 3 + 2];

        // coalesced 16B gather of this lane's feature quad
        float4 xv = *reinterpret_cast<const float4*>(x + (size_t)c * FF + fbase);
        float xvj[4] = {xv.x, xv.y, xv.z, xv.w};

        float v[4];
#pragma unroll
        for (int j = 0; j < 4; j++) {
            float d0 = p0 - mu0[j];
            float d1 = p1 - mu1[j];
            float d2 = p2 - mu2[j];
            float lw = d0 * d0 * c0[j] + d1 * d1 * c1[j] + d2 * d2 * c2[j];
            v[j] = __expf(lw) * xvj[j];
        }

        float* dst = g_accum + (size_t)r * FF + fbase;
        asm volatile("red.global.add.v4.f32 [%0], {%1, %2, %3, %4};"
                     :: "l"(dst), "f"(v[0]), "f"(v[1]), "f"(v[2]), "f"(v[3])
                     : "memory");
    }
}

// ---------------------------------------------------------------------------
// Linear epilogue v3: W via padded smem -> registers; 2-node unroll with
// 4-way split accumulators to break the serial FFMA chain.
// ---------------------------------------------------------------------------
__global__ void __launch_bounds__(256) linear_kernel(
    const float* __restrict__ W,
    const float* __restrict__ b,
    float* __restrict__ out,
    int N) {
    __shared__ float Ws[FF][FF + 1];
    __shared__ float bs[OO];

    const int tid = threadIdx.x;
    for (int i = tid; i < FF * OO; i += blockDim.x)
        Ws[i >> 5][i & 31] = W[i];
    if (tid < OO) bs[tid] = b[tid];
    __syncthreads();

    const int lane = tid & 31;
    float w[FF];
#pragma unroll
    for (int f = 0; f < FF; f++) w[f] = Ws[lane][f];
    const float bias = bs[lane];

    const int warp = (blockIdx.x * blockDim.x + tid) >> 5;
    const int nwarps = (gridDim.x * blockDim.x) >> 5;

    int n = warp;
    for (; n + nwarps < N; n += 2 * nwarps) {
        int n2 = n + nwarps;
        float a  = g_accum[(size_t)n  * FF + lane];
        float a2 = g_accum[(size_t)n2 * FF + lane];
        float s0 = bias, s1 = 0.f, s2 = 0.f, s3 = 0.f;
        float t0 = bias, t1 = 0.f, t2 = 0.f, t3 = 0.f;
#pragma unroll
        for (int f = 0; f < FF; f += 4) {
            s0 += __shfl_sync(0xffffffffu, a, f + 0) * w[f + 0];
            s1 += __shfl_sync(0xffffffffu, a, f + 1) * w[f + 1];
            s2 += __shfl_sync(0xffffffffu, a, f + 2) * w[f + 2];
            s3 += __shfl_sync(0xffffffffu, a, f + 3) * w[f + 3];
            t0 += __shfl_sync(0xffffffffu, a2, f + 0) * w[f + 0];
            t1 += __shfl_sync(0xffffffffu, a2, f + 1) * w[f + 1];
            t2 += __shfl_sync(0xffffffffu, a2, f + 2) * w[f + 2];
            t3 += __shfl_sync(0xffffffffu, a2, f + 3) * w[f + 3];
        }
        out[(size_t)n  * OO + lane] = (s0 + s1) + (s2 + s3);
        out[(size_t)n2 * OO + lane] = (t0 + t1) + (t2 + t3);
    }
    for (; n < N; n += nwarps) {
        float a = g_accum[(size_t)n * FF + lane];
        float s0 = bias, s1 = 0.f, s2 = 0.f, s3 = 0.f;
#pragma unroll
        for (int f = 0; f < FF; f += 4) {
            s0 += __shfl_sync(0xffffffffu, a, f + 0) * w[f + 0];
            s1 += __shfl_sync(0xffffffffu, a, f + 1) * w[f + 1];
            s2 += __shfl_sync(0xffffffffu, a, f + 2) * w[f + 2];
            s3 += __shfl_sync(0xffffffffu, a, f + 3) * w[f + 3];
        }
        out[(size_t)n * OO + lane] = (s0 + s1) + (s2 + s3);
    }
}

// ---------------------------------------------------------------------------
extern "C" void kernel_launch(void* const* d_in, const int* in_sizes, int n_in,
                              void* d_out, int out_size) {
    const float* x   = (const float*)d_in[0];
    const void*  ei  = d_in[1];
    const float* ps  = (const float*)d_in[2];
    const float* mu  = (const float*)d_in[3];
    const float* sg  = (const float*)d_in[4];
    const float* W   = (const float*)d_in[5];
    const float* b   = (const float*)d_in[6];
    float*       out = (float*)d_out;

    const int E = in_sizes[1] / 2;
    const int N = in_sizes[0] / FF;

    prep_kernel<<<1, 128>>>(mu, sg, (const int*)ei, in_sizes[1]);
    zero_kernel<<<800, 256>>>();

    edge_kernel<<<148 * 8, 256>>>(x, ei, ps, E);

    linear_kernel<<<148 * 8, 256>>>(W, b, out, N);
}

// round 5
// speedup vs baseline: 5.5410x; 1.0569x over previous
#include <cuda_runtime.h>
#include <cstdint>

#define NN 100000
#define FF 32
#define DD 3
#define OO 32

__device__ float g_accum[NN * FF];
__device__ float g_mu_t[DD * FF];   // [d][f]
__device__ float g_c_t[DD * FF];    // [d][f] = -0.5*log2(e) / (1e-14 + sigma^2)
__device__ int   g_is64;            // edge_index dtype flag (1 = int64)

// ---------------------------------------------------------------------------
__global__ void prep_kernel(const float* __restrict__ mu,
                            const float* __restrict__ sigma,
                            const int* __restrict__ ei32,
                            int total_elems) {
    int t = threadIdx.x;
    if (t < DD * FF) {
        int d = t / FF;
        int f = t % FF;
        float m = mu[f * DD + d];
        float s = sigma[f * DD + d];
        g_mu_t[d * FF + f] = m;
        // fold log2(e) so the edge kernel can use exp2f directly
        g_c_t[d * FF + f]  = -0.5f * 1.4426950408889634f / (1e-14f + s * s);
    }
    if (t == 0) {
        // int64 little-endian with values < 2^31 => every odd 32-bit word is 0
        int all_zero = 1;
        int limit = 2 * total_elems;
        for (int i = 1; i < 257 && i < limit; i += 2) {
            if (ei32[i] != 0) { all_zero = 0; break; }
        }
        g_is64 = all_zero;
    }
}

// ---------------------------------------------------------------------------
__global__ void zero_kernel() {
    int i = blockIdx.x * blockDim.x + threadIdx.x;
    int total4 = (NN * FF) / 4;
    float4 z = make_float4(0.f, 0.f, 0.f, 0.f);
    float4* p = reinterpret_cast<float4*>(g_accum);
    for (; i < total4; i += gridDim.x * blockDim.x) p[i] = z;
}

// ---------------------------------------------------------------------------
// Edge kernel v3: 8 edges per warp-iteration, cooperative loading.
//   lane = 8*g + q : g = edge slot (0..3), q = feature quad (0..7)
//   Edge pair per lane: eA = eb+g, eB = eb+4+g.
// Index load: ONE LDG (lanes 0-7: row idx, lanes 8-15: col idx).
// Pseudo load: ONE LDG (lanes 0-23: 24 consecutive floats = 8 edges x 3).
// Distribute via SHFL. Two independent gather->RED chains for MLP.
// ---------------------------------------------------------------------------
__global__ void __launch_bounds__(256) edge_kernel(
    const float* __restrict__ x,
    const void* __restrict__ edge_index,
    const float* __restrict__ pseudo,
    int E) {
    const int lane  = threadIdx.x & 31;
    const int g     = lane >> 3;
    const int q     = lane & 7;
    const int fbase = q * 4;
    const int warp  = (blockIdx.x * blockDim.x + threadIdx.x) >> 5;
    const int nwarps = (gridDim.x * blockDim.x) >> 5;
    const unsigned FULL = 0xffffffffu;

    const int is64 = g_is64;
    const int* __restrict__ ei32 = (const int*)edge_index;
    const long long* __restrict__ ei64 = (const long long*)edge_index;

    float mu0[4], mu1[4], mu2[4], c0[4], c1[4], c2[4];
#pragma unroll
    for (int j = 0; j < 4; j++) {
        mu0[j] = g_mu_t[0 * FF + fbase + j];
        mu1[j] = g_mu_t[1 * FF + fbase + j];
        mu2[j] = g_mu_t[2 * FF + fbase + j];
        c0[j]  = g_c_t[0 * FF + fbase + j];
        c1[j]  = g_c_t[1 * FF + fbase + j];
        c2[j]  = g_c_t[2 * FF + fbase + j];
    }

    for (long long eb = (long long)warp * 8; eb < E; eb += (long long)nwarps * 8) {
        // ---- cooperative index load: lanes 0-7 rows, 8-15 cols ----
        int idx = 0;
        {
            long long epos = eb + (lane & 7);
            if (lane < 16 && epos < E) {
                long long a = (lane < 8) ? epos : epos + (long long)E;
                idx = is64 ? (int)ei64[a] : ei32[a];
            }
        }
        // ---- cooperative pseudo load: lanes 0-23, contiguous ----
        float pv = 0.f;
        {
            long long ppos = eb * 3 + lane;
            if (lane < 24 && ppos < (long long)E * 3) pv = pseudo[ppos];
        }

        const int rA = __shfl_sync(FULL, idx, g);
        const int rB = __shfl_sync(FULL, idx, 4 + g);
        const int cA = __shfl_sync(FULL, idx, 8 + g);
        const int cB = __shfl_sync(FULL, idx, 12 + g);
        const float p0A = __shfl_sync(FULL, pv, 3 * g + 0);
        const float p1A = __shfl_sync(FULL, pv, 3 * g + 1);
        const float p2A = __shfl_sync(FULL, pv, 3 * g + 2);
        const float p0B = __shfl_sync(FULL, pv, 12 + 3 * g + 0);
        const float p1B = __shfl_sync(FULL, pv, 12 + 3 * g + 1);
        const float p2B = __shfl_sync(FULL, pv, 12 + 3 * g + 2);

        const bool aval = (eb + g) < E;
        const bool bval = (eb + 4 + g) < E;

        // two independent gathers (each: 8 lanes cover one 128B row)
        float4 xa = make_float4(0.f, 0.f, 0.f, 0.f);
        float4 xb = make_float4(0.f, 0.f, 0.f, 0.f);
        if (aval) xa = *reinterpret_cast<const float4*>(x + (size_t)cA * FF + fbase);
        if (bval) xb = *reinterpret_cast<const float4*>(x + (size_t)cB * FF + fbase);

        float xaj[4] = {xa.x, xa.y, xa.z, xa.w};
        float xbj[4] = {xb.x, xb.y, xb.z, xb.w};
        float vA[4], vB[4];
#pragma unroll
        for (int j = 0; j < 4; j++) {
            float d0 = p0A - mu0[j], d1 = p1A - mu1[j], d2 = p2A - mu2[j];
            float lw = d0 * d0 * c0[j] + d1 * d1 * c1[j] + d2 * d2 * c2[j];
            vA[j] = exp2f(lw) * xaj[j];
        }
#pragma unroll
        for (int j = 0; j < 4; j++) {
            float d0 = p0B - mu0[j], d1 = p1B - mu1[j], d2 = p2B - mu2[j];
            float lw = d0 * d0 * c0[j] + d1 * d1 * c1[j] + d2 * d2 * c2[j];
            vB[j] = exp2f(lw) * xbj[j];
        }

        if (aval) {
            float* dst = g_accum + (size_t)rA * FF + fbase;
            asm volatile("red.global.add.v4.f32 [%0], {%1, %2, %3, %4};"
                         :: "l"(dst), "f"(vA[0]), "f"(vA[1]), "f"(vA[2]), "f"(vA[3])
                         : "memory");
        }
        if (bval) {
            float* dst = g_accum + (size_t)rB * FF + fbase;
            asm volatile("red.global.add.v4.f32 [%0], {%1, %2, %3, %4};"
                         :: "l"(dst), "f"(vB[0]), "f"(vB[1]), "f"(vB[2]), "f"(vB[3])
                         : "memory");
        }
    }
}

// ---------------------------------------------------------------------------
// Linear epilogue (unchanged from R4): W via padded smem -> registers;
// 2-node unroll with 4-way split accumulators.
// ---------------------------------------------------------------------------
__global__ void __launch_bounds__(256) linear_kernel(
    const float* __restrict__ W,
    const float* __restrict__ b,
    float* __restrict__ out,
    int N) {
    __shared__ float Ws[FF][FF + 1];
    __shared__ float bs[OO];

    const int tid = threadIdx.x;
    for (int i = tid; i < FF * OO; i += blockDim.x)
        Ws[i >> 5][i & 31] = W[i];
    if (tid < OO) bs[tid] = b[tid];
    __syncthreads();

    const int lane = tid & 31;
    float w[FF];
#pragma unroll
    for (int f = 0; f < FF; f++) w[f] = Ws[lane][f];
    const float bias = bs[lane];

    const int warp = (blockIdx.x * blockDim.x + tid) >> 5;
    const int nwarps = (gridDim.x * blockDim.x) >> 5;

    int n = warp;
    for (; n + nwarps < N; n += 2 * nwarps) {
        int n2 = n + nwarps;
        float a  = g_accum[(size_t)n  * FF + lane];
        float a2 = g_accum[(size_t)n2 * FF + lane];
        float s0 = bias, s1 = 0.f, s2 = 0.f, s3 = 0.f;
        float t0 = bias, t1 = 0.f, t2 = 0.f, t3 = 0.f;
#pragma unroll
        for (int f = 0; f < FF; f += 4) {
            s0 += __shfl_sync(0xffffffffu, a, f + 0) * w[f + 0];
            s1 += __shfl_sync(0xffffffffu, a, f + 1) * w[f + 1];
            s2 += __shfl_sync(0xffffffffu, a, f + 2) * w[f + 2];
            s3 += __shfl_sync(0xffffffffu, a, f + 3) * w[f + 3];
            t0 += __shfl_sync(0xffffffffu, a2, f + 0) * w[f + 0];
            t1 += __shfl_sync(0xffffffffu, a2, f + 1) * w[f + 1];
            t2 += __shfl_sync(0xffffffffu, a2, f + 2) * w[f + 2];
            t3 += __shfl_sync(0xffffffffu, a2, f + 3) * w[f + 3];
        }
        out[(size_t)n  * OO + lane] = (s0 + s1) + (s2 + s3);
        out[(size_t)n2 * OO + lane] = (t0 + t1) + (t2 + t3);
    }
    for (; n < N; n += nwarps) {
        float a = g_accum[(size_t)n * FF + lane];
        float s0 = bias, s1 = 0.f, s2 = 0.f, s3 = 0.f;
#pragma unroll
        for (int f = 0; f < FF; f += 4) {
            s0 += __shfl_sync(0xffffffffu, a, f + 0) * w[f + 0];
            s1 += __shfl_sync(0xffffffffu, a, f + 1) * w[f + 1];
            s2 += __shfl_sync(0xffffffffu, a, f + 2) * w[f + 2];
            s3 += __shfl_sync(0xffffffffu, a, f + 3) * w[f + 3];
        }
        out[(size_t)n * OO + lane] = (s0 + s1) + (s2 + s3);
    }
}

// ---------------------------------------------------------------------------
extern "C" void kernel_launch(void* const* d_in, const int* in_sizes, int n_in,
                              void* d_out, int out_size) {
    const float* x   = (const float*)d_in[0];
    const void*  ei  = d_in[1];
    const float* ps  = (const float*)d_in[2];
    const float* mu  = (const float*)d_in[3];
    const float* sg  = (const float*)d_in[4];
    const float* W   = (const float*)d_in[5];
    const float* b   = (const float*)d_in[6];
    float*       out = (float*)d_out;

    const int E = in_sizes[1] / 2;
    const int N = in_sizes[0] / FF;

    prep_kernel<<<1, 128>>>(mu, sg, (const int*)ei, in_sizes[1]);
    zero_kernel<<<800, 256>>>();

    edge_kernel<<<148 * 8, 256>>>(x, ei, ps, E);

    linear_kernel<<<148 * 8, 256>>>(W, b, out, N);
}